// round 10
// baseline (speedup 1.0000x reference)
#include <cuda_runtime.h>
#include <cstdint>

// ---------------------------------------------------------------------------
// BasicConvolutionBlock: sparse conv (gather-GEMM, K=27, Cin=Cout=64) + BN + ReLU
// mma.sync tf32 (compute_100-safe). 4 warps x 48-row tiles, M_TILE=192:
// cuts per-row B fragment re-reads vs R8 while staying at 128KB smem.
//   d_in[0] feats [N,64] f32      d_in[1] W [27,64,64] f32
//   d_in[2] gamma [64]            d_in[3] beta [64]
//   d_in[4] nbr_idx [27,N] i32    d_in[5] mask [27,N] i32
// out: [N,64] f32
// ---------------------------------------------------------------------------

#define CIN   64
#define COUT  64
#define MAXK  27
#define M_TILE 192
#define CTA   128
#define BN_EPS 1e-5f

// dynamic smem: A double-buffer (2 x 48KB) + WT double-buffer (2 x 16KB)
#define A_OFF0 0u
#define A_OFF1 49152u
#define B_OFF0 98304u
#define B_OFF1 114688u
#define SMEM_BYTES 131072

__device__ float g_stats[128];              // [0:64) sum, [64:128) sumsq
__device__ float g_wt[MAXK * CIN * COUT];   // tf32-rounded W, transposed [k][cout][cin]

// ---------------- helpers ---------------------------------------------------
__device__ __forceinline__ float to_tf32(float x) {
    uint32_t r;
    asm("cvt.rna.tf32.f32 %0, %1;" : "=r"(r) : "f"(x));
    return __uint_as_float(r);
}

__device__ __forceinline__ uint32_t smem_u32(const void* p) {
    uint32_t a;
    asm("{ .reg .u64 t; cvta.to.shared.u64 t, %1; cvt.u32.u64 %0, t; }"
        : "=r"(a) : "l"(p));
    return a;
}

__device__ __forceinline__ void cpa16(uint32_t dst, const void* src, uint32_t sz) {
    asm volatile("cp.async.cg.shared.global [%0], [%1], 16, %2;"
                 :: "r"(dst), "l"(src), "r"(sz) : "memory");
}
#define CP_COMMIT() asm volatile("cp.async.commit_group;" ::: "memory")
#define CP_WAIT0()  asm volatile("cp.async.wait_group 0;" ::: "memory")

// swizzled float4 index inside a [rows][64-float] tile
__device__ __forceinline__ uint32_t swz4(int r, int q) {
    return (uint32_t)(r * 16 + (q ^ (r & 7)));
}

// ---------------------------------------------------------------------------
__global__ void zero_stats_kernel() {
    int t = threadIdx.x;
    if (t < 128) g_stats[t] = 0.0f;
}

__global__ void prep_w_kernel(const float* __restrict__ w) {
    int k = blockIdx.x;
    const float* ws = w + (size_t)k * CIN * COUT;
    float* wd = g_wt + (size_t)k * CIN * COUT;
    for (int e = threadIdx.x; e < CIN * COUT; e += blockDim.x) {
        int ci = e >> 6, co = e & 63;
        wd[co * 64 + ci] = to_tf32(ws[e]);   // transpose: [cout][cin]
    }
}

// ---------------------------------------------------------------------------
// Conv kernel: CTA = 128 thr (4 warps), tile = 192 rows. Warp w owns rows
// [w*48, w*48+48) as three m16 sub-tiles. k-offsets accumulated in registers.
// ---------------------------------------------------------------------------
__global__ void __launch_bounds__(CTA, 1)
conv_kernel(const float* __restrict__ feats,
            const int* __restrict__ nbr,
            const int* __restrict__ mask,
            float*     __restrict__ out,
            int n, int kk) {
    extern __shared__ char smem[];
    __shared__ float sst[128];
    const uint32_t sb = smem_u32(smem);

    const int tid  = threadIdx.x;
    const int warp = tid >> 5, lane = tid & 31;
    const int lr = lane >> 2, le = lane & 3;
    const int cb = blockIdx.x * M_TILE;

    if (tid < 128) sst[tid] = 0.0f;

    const int r0 = tid;                    // every thread: row tid
    const int r1 = 128 + tid;              // threads < 64: row 128+tid
    const bool has2 = (tid < 64);
    const int g0 = cb + r0, g1 = cb + r1;

    const uint32_t a_off[2] = {A_OFF0, A_OFF1};
    const uint32_t b_off[2] = {B_OFF0, B_OFF1};

    // --- idx/mask prefetch (depth 2) + stage 0 issue -------------------------
    int pn0 = 0, pn1 = 0; uint32_t pv0 = 0, pv1 = 0;
    if (g0 < n) { pv0 = (uint32_t)mask[g0]; pn0 = nbr[g0]; }
    if (has2 && g1 < n) { pv1 = (uint32_t)mask[g1]; pn1 = nbr[g1]; }

    {
        uint32_t abase = sb + a_off[0];
        const char* s0 = (const char*)(feats + (size_t)pn0 * CIN);
        uint32_t z0 = pv0 ? 16u : 0u;
#pragma unroll
        for (int j = 0; j < 16; ++j)
            cpa16(abase + (swz4(r0, j) << 4), s0 + j * 16, z0);
        if (has2) {
            const char* s1 = (const char*)(feats + (size_t)pn1 * CIN);
            uint32_t z1 = pv1 ? 16u : 0u;
#pragma unroll
            for (int j = 0; j < 16; ++j)
                cpa16(abase + (swz4(r1, j) << 4), s1 + j * 16, z1);
        }
        const char* wsrc = (const char*)g_wt;
        uint32_t bbase = sb + b_off[0];
#pragma unroll
        for (int j = 0; j < 8; ++j) {
            int e4 = tid + j * CTA;
            cpa16(bbase + (swz4(e4 >> 4, e4 & 15) << 4), wsrc + e4 * 16, 16u);
        }
        CP_COMMIT();
    }

    if (kk > 1) {
        pv0 = 0; pv1 = 0; pn0 = 0; pn1 = 0;
        if (g0 < n) { int o = n + g0; pv0 = (uint32_t)mask[o]; pn0 = nbr[o]; }
        if (has2 && g1 < n) { int o = n + g1; pv1 = (uint32_t)mask[o]; pn1 = nbr[o]; }
    }

    float acc[8][3][4];            // [nt][row-subtile][frag]
#pragma unroll
    for (int nt = 0; nt < 8; ++nt)
#pragma unroll
        for (int t = 0; t < 3; ++t)
#pragma unroll
            for (int j = 0; j < 4; ++j) acc[nt][t][j] = 0.0f;

    const int ra = warp * 48 + lr; // subtile0 fragment row; subtile t = +16t

    for (int k = 0; k < kk; ++k) {
        CP_WAIT0();
        __syncthreads();

        // issue stage k+1 using prefetched idx/mask
        if (k + 1 < kk) {
            const int buf = (k + 1) & 1;
            uint32_t abase = sb + a_off[buf];
            const char* s0 = (const char*)(feats + (size_t)pn0 * CIN);
            uint32_t z0 = pv0 ? 16u : 0u;
#pragma unroll
            for (int j = 0; j < 16; ++j)
                cpa16(abase + (swz4(r0, j) << 4), s0 + j * 16, z0);
            if (has2) {
                const char* s1 = (const char*)(feats + (size_t)pn1 * CIN);
                uint32_t z1 = pv1 ? 16u : 0u;
#pragma unroll
                for (int j = 0; j < 16; ++j)
                    cpa16(abase + (swz4(r1, j) << 4), s1 + j * 16, z1);
            }
            const char* wsrc = (const char*)(g_wt + (size_t)(k + 1) * CIN * COUT);
            uint32_t bbase = sb + b_off[buf];
#pragma unroll
            for (int j = 0; j < 8; ++j) {
                int e4 = tid + j * CTA;
                cpa16(bbase + (swz4(e4 >> 4, e4 & 15) << 4), wsrc + e4 * 16, 16u);
            }
            CP_COMMIT();
        }
        // prefetch idx/mask for stage k+2
        if (k + 2 < kk) {
            int ob = (k + 2) * n;
            pv0 = 0; pv1 = 0; pn0 = 0; pn1 = 0;
            if (g0 < n) { int o = ob + g0; pv0 = (uint32_t)mask[o]; pn0 = nbr[o]; }
            if (has2 && g1 < n) { int o = ob + g1; pv1 = (uint32_t)mask[o]; pn1 = nbr[o]; }
        }

        // ---- compute from buffer k&1 ----
        const char* Ap = smem + a_off[k & 1];
        const char* Bp = smem + b_off[k & 1];
#pragma unroll
        for (int ks = 0; ks < 8; ++ks) {
            const uint32_t bq = (uint32_t)((((2 * ks) ^ lr) << 4) + (le << 2));
            const uint32_t base = (uint32_t)(ra << 8) + bq;
            uint32_t af[3][4];
#pragma unroll
            for (int t = 0; t < 3; ++t) {
                const uint32_t o = base + (uint32_t)(t * 4096);
                af[t][0] = *(const uint32_t*)(Ap + o);
                af[t][1] = *(const uint32_t*)(Ap + o + 2048);
                af[t][2] = *(const uint32_t*)(Ap + (o ^ 16));
                af[t][3] = *(const uint32_t*)(Ap + ((o + 2048) ^ 16));
            }
#pragma unroll
            for (int nt = 0; nt < 8; ++nt) {
                const uint32_t b0o = (uint32_t)((nt * 8 + lr) << 8) + bq;
                uint32_t b0 = *(const uint32_t*)(Bp + b0o);
                uint32_t b1 = *(const uint32_t*)(Bp + (b0o ^ 16));
#pragma unroll
                for (int t = 0; t < 3; ++t) {
                    asm volatile(
                        "mma.sync.aligned.m16n8k8.row.col.f32.tf32.tf32.f32 "
                        "{%0,%1,%2,%3}, {%4,%5,%6,%7}, {%8,%9}, {%0,%1,%2,%3};"
                        : "+f"(acc[nt][t][0]), "+f"(acc[nt][t][1]),
                          "+f"(acc[nt][t][2]), "+f"(acc[nt][t][3])
                        : "r"(af[t][0]), "r"(af[t][1]), "r"(af[t][2]), "r"(af[t][3]),
                          "r"(b0), "r"(b1));
                }
            }
        }
    }

    // ---- BN partial stats from register fragments (invalid rows hold 0) ----
#pragma unroll
    for (int nt = 0; nt < 8; ++nt) {
        float s0 = 0.f, q0 = 0.f, s1 = 0.f, q1 = 0.f;
#pragma unroll
        for (int t = 0; t < 3; ++t) {
            s0 += acc[nt][t][0] + acc[nt][t][2];
            q0 += acc[nt][t][0] * acc[nt][t][0] + acc[nt][t][2] * acc[nt][t][2];
            s1 += acc[nt][t][1] + acc[nt][t][3];
            q1 += acc[nt][t][1] * acc[nt][t][1] + acc[nt][t][3] * acc[nt][t][3];
        }
#pragma unroll
        for (int d = 4; d <= 16; d <<= 1) {
            s0 += __shfl_xor_sync(0xffffffffu, s0, d);
            q0 += __shfl_xor_sync(0xffffffffu, q0, d);
            s1 += __shfl_xor_sync(0xffffffffu, s1, d);
            q1 += __shfl_xor_sync(0xffffffffu, q1, d);
        }
        if (lane < 4) {
            int c0 = nt * 8 + lane * 2;
            atomicAdd(&sst[c0], s0);      atomicAdd(&sst[64 + c0], q0);
            atomicAdd(&sst[c0 + 1], s1);  atomicAdd(&sst[64 + c0 + 1], q1);
        }
    }

    // ---- fragments -> smem (swizzled) -> coalesced global write ----
    __syncthreads();
    {
        char* Sp = smem;   // reuse buffer A0 (48 KB for 192 rows)
#pragma unroll
        for (int nt = 0; nt < 8; ++nt) {
            int col = nt * 8 + le * 2;
            int q = col >> 2, e = col & 3;
#pragma unroll
            for (int t = 0; t < 3; ++t) {
                int row = warp * 48 + t * 16 + lr;
                uint32_t o0 = (swz4(row, q) << 4) + (uint32_t)(e * 4);
                *(float2*)(Sp + o0)        = make_float2(acc[nt][t][0], acc[nt][t][1]);
                *(float2*)(Sp + o0 + 2048) = make_float2(acc[nt][t][2], acc[nt][t][3]);
            }
        }
    }
    __syncthreads();
    {
        const char* Sp = smem;
#pragma unroll
        for (int it = 0; it < 24; ++it) {
            int rl = (tid >> 4) + it * 8;
            int q = tid & 15;
            float4 v = *(const float4*)(Sp + (swz4(rl, q) << 4));
            int gr = cb + rl;
            if (gr < n) ((float4*)out)[(size_t)gr * 16 + q] = v;
        }
    }
    if (tid < 128) atomicAdd(&g_stats[tid], sst[tid]);
}

// ---------------------------------------------------------------------------
__global__ void bn_relu_kernel(float* __restrict__ out,
                               const float* __restrict__ gamma,
                               const float* __restrict__ beta,
                               int n) {
    __shared__ float sc[COUT], bi[COUT];
    const int tid = threadIdx.x;
    if (tid < COUT) {
        float inv_n = 1.0f / (float)n;
        float mean = g_stats[tid] * inv_n;
        float var = fmaxf(g_stats[64 + tid] * inv_n - mean * mean, 0.0f);
        float inv = rsqrtf(var + BN_EPS);
        float scl = gamma[tid] * inv;
        sc[tid] = scl;
        bi[tid] = beta[tid] - mean * scl;
    }
    __syncthreads();

    const int total = n * (COUT / 4);
    float4* o4 = (float4*)out;
    for (int i = blockIdx.x * blockDim.x + tid; i < total;
         i += gridDim.x * blockDim.x) {
        float4 v = o4[i];
        int c = (i & 15) << 2;
        v.x = fmaxf(fmaf(v.x, sc[c],     bi[c]),     0.f);
        v.y = fmaxf(fmaf(v.y, sc[c + 1], bi[c + 1]), 0.f);
        v.z = fmaxf(fmaf(v.z, sc[c + 2], bi[c + 2]), 0.f);
        v.w = fmaxf(fmaf(v.w, sc[c + 3], bi[c + 3]), 0.f);
        o4[i] = v;
    }
}

// ---------------------------------------------------------------------------
extern "C" void kernel_launch(void* const* d_in, const int* in_sizes, int n_in,
                              void* d_out, int out_size) {
    const float* feats = (const float*)d_in[0];
    const float* Wg    = (const float*)d_in[1];
    const float* gamma = (const float*)d_in[2];
    const float* beta  = (const float*)d_in[3];
    const int*   nbr   = (const int*)d_in[4];
    const int*   mask  = (const int*)d_in[5];
    float* out = (float*)d_out;

    const int n  = in_sizes[0] / CIN;              // 200000
    const int kk = in_sizes[1] / (CIN * COUT);     // 27

    cudaFuncSetAttribute(conv_kernel,
                         cudaFuncAttributeMaxDynamicSharedMemorySize,
                         SMEM_BYTES);

    zero_stats_kernel<<<1, 128>>>();
    prep_w_kernel<<<kk, 256>>>(Wg);

    const int grid = (n + M_TILE - 1) / M_TILE;    // 1042
    conv_kernel<<<grid, CTA, SMEM_BYTES>>>(feats, nbr, mask, out, n, kk);

    int bn_grid = (n * (COUT / 4) + 255) / 256;
    if (bn_grid > 1184) bn_grid = 1184;
    bn_relu_kernel<<<bn_grid, 256>>>(out, gamma, beta, n);
}

// round 11
// speedup vs baseline: 1.1679x; 1.1679x over previous
#include <cuda_runtime.h>
#include <cstdint>

// ---------------------------------------------------------------------------
// BasicConvolutionBlock: sparse conv (gather-GEMM, K=27, Cin=Cout=64) + BN + ReLU
// mma.sync tf32 (compute_100-safe). M_TILE=192 (4 warps x 48 rows) at occ 2:
// A double-buffered (2x48KB), B single smem slot + register prefetch of W[k+1]
// during compute k. 112KB dynamic smem/CTA -> 2 CTAs/SM (R10 showed occ1 kills).
//   d_in[0] feats [N,64] f32      d_in[1] W [27,64,64] f32
//   d_in[2] gamma [64]            d_in[3] beta [64]
//   d_in[4] nbr_idx [27,N] i32    d_in[5] mask [27,N] i32
// out: [N,64] f32
// ---------------------------------------------------------------------------

#define CIN   64
#define COUT  64
#define MAXK  27
#define M_TILE 192
#define CTA   128
#define BN_EPS 1e-5f

// dynamic smem: A double-buffer (2 x 48KB) + single WT buffer (16KB)
#define A_OFF0 0u
#define A_OFF1 49152u
#define B_OFF  98304u
#define SMEM_BYTES 114688

__device__ float g_stats[128];              // [0:64) sum, [64:128) sumsq
__device__ float g_wt[MAXK * CIN * COUT];   // tf32-rounded W, transposed [k][cout][cin]

// ---------------- helpers ---------------------------------------------------
__device__ __forceinline__ float to_tf32(float x) {
    uint32_t r;
    asm("cvt.rna.tf32.f32 %0, %1;" : "=r"(r) : "f"(x));
    return __uint_as_float(r);
}

__device__ __forceinline__ uint32_t smem_u32(const void* p) {
    uint32_t a;
    asm("{ .reg .u64 t; cvta.to.shared.u64 t, %1; cvt.u32.u64 %0, t; }"
        : "=r"(a) : "l"(p));
    return a;
}

__device__ __forceinline__ void cpa16(uint32_t dst, const void* src, uint32_t sz) {
    asm volatile("cp.async.cg.shared.global [%0], [%1], 16, %2;"
                 :: "r"(dst), "l"(src), "r"(sz) : "memory");
}
#define CP_COMMIT() asm volatile("cp.async.commit_group;" ::: "memory")
#define CP_WAIT0()  asm volatile("cp.async.wait_group 0;" ::: "memory")

// swizzled float4 index inside a [rows][64-float] tile
__device__ __forceinline__ uint32_t swz4(int r, int q) {
    return (uint32_t)(r * 16 + (q ^ (r & 7)));
}

// ---------------------------------------------------------------------------
__global__ void zero_stats_kernel() {
    int t = threadIdx.x;
    if (t < 128) g_stats[t] = 0.0f;
}

__global__ void prep_w_kernel(const float* __restrict__ w) {
    int k = blockIdx.x;
    const float* ws = w + (size_t)k * CIN * COUT;
    float* wd = g_wt + (size_t)k * CIN * COUT;
    for (int e = threadIdx.x; e < CIN * COUT; e += blockDim.x) {
        int ci = e >> 6, co = e & 63;
        wd[co * 64 + ci] = to_tf32(ws[e]);   // transpose: [cout][cin]
    }
}

// ---------------------------------------------------------------------------
// Conv kernel: CTA = 128 thr (4 warps), tile = 192 rows. Warp w owns rows
// [w*48, w*48+48) as three m16 sub-tiles. k-offsets accumulated in registers.
// ---------------------------------------------------------------------------
__global__ void __launch_bounds__(CTA, 2)
conv_kernel(const float* __restrict__ feats,
            const int* __restrict__ nbr,
            const int* __restrict__ mask,
            float*     __restrict__ out,
            int n, int kk) {
    extern __shared__ char smem[];
    const uint32_t sb = smem_u32(smem);

    const int tid  = threadIdx.x;
    const int warp = tid >> 5, lane = tid & 31;
    const int lr = lane >> 2, le = lane & 3;
    const int cb = blockIdx.x * M_TILE;

    const int r0 = tid;                    // every thread: row tid
    const int r1 = 128 + tid;              // threads < 64: row 128+tid
    const bool has2 = (tid < 64);
    const int g0 = cb + r0, g1 = cb + r1;

    const uint32_t a_off[2] = {A_OFF0, A_OFF1};
    const uint32_t bbase = sb + B_OFF;

    // --- idx/mask prefetch (depth 2) + stage 0 issue -------------------------
    int pn0 = 0, pn1 = 0; uint32_t pv0 = 0, pv1 = 0;
    if (g0 < n) { pv0 = (uint32_t)mask[g0]; pn0 = nbr[g0]; }
    if (has2 && g1 < n) { pv1 = (uint32_t)mask[g1]; pn1 = nbr[g1]; }

    {
        uint32_t abase = sb + a_off[0];
        const char* s0 = (const char*)(feats + (size_t)pn0 * CIN);
        uint32_t z0 = pv0 ? 16u : 0u;
#pragma unroll
        for (int j = 0; j < 16; ++j)
            cpa16(abase + (swz4(r0, j) << 4), s0 + j * 16, z0);
        if (has2) {
            const char* s1 = (const char*)(feats + (size_t)pn1 * CIN);
            uint32_t z1 = pv1 ? 16u : 0u;
#pragma unroll
            for (int j = 0; j < 16; ++j)
                cpa16(abase + (swz4(r1, j) << 4), s1 + j * 16, z1);
        }
        // stage W[0] into the single B buffer
        const char* wsrc = (const char*)g_wt;
#pragma unroll
        for (int j = 0; j < 8; ++j) {
            int e4 = tid + j * CTA;
            cpa16(bbase + (swz4(e4 >> 4, e4 & 15) << 4), wsrc + e4 * 16, 16u);
        }
        CP_COMMIT();
    }

    if (kk > 1) {
        pv0 = 0; pv1 = 0; pn0 = 0; pn1 = 0;
        if (g0 < n) { int o = n + g0; pv0 = (uint32_t)mask[o]; pn0 = nbr[o]; }
        if (has2 && g1 < n) { int o = n + g1; pv1 = (uint32_t)mask[o]; pn1 = nbr[o]; }
    }

    float acc[8][3][4];            // [nt][row-subtile][frag]
#pragma unroll
    for (int nt = 0; nt < 8; ++nt)
#pragma unroll
        for (int t = 0; t < 3; ++t)
#pragma unroll
            for (int j = 0; j < 4; ++j) acc[nt][t][j] = 0.0f;

    const int ra = warp * 48 + lr; // subtile0 fragment row; subtile t = +16t

    CP_WAIT0();
    __syncthreads();               // A(0) + B(0) visible

    for (int k = 0; k < kk; ++k) {
        float4 breg[8];
        // issue A(k+1) gathers; prefetch W[k+1] into registers
        if (k + 1 < kk) {
            uint32_t abase = sb + a_off[(k + 1) & 1];
            const char* s0 = (const char*)(feats + (size_t)pn0 * CIN);
            uint32_t z0 = pv0 ? 16u : 0u;
#pragma unroll
            for (int j = 0; j < 16; ++j)
                cpa16(abase + (swz4(r0, j) << 4), s0 + j * 16, z0);
            if (has2) {
                const char* s1 = (const char*)(feats + (size_t)pn1 * CIN);
                uint32_t z1 = pv1 ? 16u : 0u;
#pragma unroll
                for (int j = 0; j < 16; ++j)
                    cpa16(abase + (swz4(r1, j) << 4), s1 + j * 16, z1);
            }
            CP_COMMIT();
            const float4* wsrc = (const float4*)(g_wt + (size_t)(k + 1) * CIN * COUT);
#pragma unroll
            for (int j = 0; j < 8; ++j)
                breg[j] = wsrc[tid + j * CTA];
        }
        // prefetch idx/mask for stage k+2
        if (k + 2 < kk) {
            int ob = (k + 2) * n;
            pv0 = 0; pv1 = 0; pn0 = 0; pn1 = 0;
            if (g0 < n) { int o = ob + g0; pv0 = (uint32_t)mask[o]; pn0 = nbr[o]; }
            if (has2 && g1 < n) { int o = ob + g1; pv1 = (uint32_t)mask[o]; pn1 = nbr[o]; }
        }

        // ---- compute k from A buf k&1 and the single B buffer ----
        const char* Ap = smem + a_off[k & 1];
        const char* Bp = smem + B_OFF;
#pragma unroll
        for (int ks = 0; ks < 8; ++ks) {
            const uint32_t bq = (uint32_t)((((2 * ks) ^ lr) << 4) + (le << 2));
            const uint32_t base = (uint32_t)(ra << 8) + bq;
            uint32_t af[3][4];
#pragma unroll
            for (int t = 0; t < 3; ++t) {
                const uint32_t o = base + (uint32_t)(t * 4096);
                af[t][0] = *(const uint32_t*)(Ap + o);
                af[t][1] = *(const uint32_t*)(Ap + o + 2048);
                af[t][2] = *(const uint32_t*)(Ap + (o ^ 16));
                af[t][3] = *(const uint32_t*)(Ap + ((o + 2048) ^ 16));
            }
#pragma unroll
            for (int nt = 0; nt < 8; ++nt) {
                const uint32_t b0o = (uint32_t)((nt * 8 + lr) << 8) + bq;
                uint32_t b0 = *(const uint32_t*)(Bp + b0o);
                uint32_t b1 = *(const uint32_t*)(Bp + (b0o ^ 16));
#pragma unroll
                for (int t = 0; t < 3; ++t) {
                    asm volatile(
                        "mma.sync.aligned.m16n8k8.row.col.f32.tf32.tf32.f32 "
                        "{%0,%1,%2,%3}, {%4,%5,%6,%7}, {%8,%9}, {%0,%1,%2,%3};"
                        : "+f"(acc[nt][t][0]), "+f"(acc[nt][t][1]),
                          "+f"(acc[nt][t][2]), "+f"(acc[nt][t][3])
                        : "r"(af[t][0]), "r"(af[t][1]), "r"(af[t][2]), "r"(af[t][3]),
                          "r"(b0), "r"(b1));
                }
            }
        }

        // ---- rotate B: all warps done reading B(k); store W[k+1] ----
        if (k + 1 < kk) {
            __syncthreads();
#pragma unroll
            for (int j = 0; j < 8; ++j) {
                int e4 = tid + j * CTA;
                *(float4*)(smem + B_OFF + (swz4(e4 >> 4, e4 & 15) << 4)) = breg[j];
            }
            CP_WAIT0();            // A(k+1) gathers complete
            __syncthreads();       // A(k+1) + B(k+1) visible to all
        }
    }

    // ---- BN partial stats from register fragments (invalid rows hold 0) ----
#pragma unroll
    for (int nt = 0; nt < 8; ++nt) {
        float s0 = 0.f, q0 = 0.f, s1 = 0.f, q1 = 0.f;
#pragma unroll
        for (int t = 0; t < 3; ++t) {
            s0 += acc[nt][t][0] + acc[nt][t][2];
            q0 += acc[nt][t][0] * acc[nt][t][0] + acc[nt][t][2] * acc[nt][t][2];
            s1 += acc[nt][t][1] + acc[nt][t][3];
            q1 += acc[nt][t][1] * acc[nt][t][1] + acc[nt][t][3] * acc[nt][t][3];
        }
#pragma unroll
        for (int d = 4; d <= 16; d <<= 1) {
            s0 += __shfl_xor_sync(0xffffffffu, s0, d);
            q0 += __shfl_xor_sync(0xffffffffu, q0, d);
            s1 += __shfl_xor_sync(0xffffffffu, s1, d);
            q1 += __shfl_xor_sync(0xffffffffu, q1, d);
        }
        if (lane < 4) {
            int c0 = nt * 8 + lane * 2;
            atomicAdd(&g_stats[c0], s0);      atomicAdd(&g_stats[64 + c0], q0);
            atomicAdd(&g_stats[c0 + 1], s1);  atomicAdd(&g_stats[64 + c0 + 1], q1);
        }
    }

    // ---- fragments -> smem (swizzled) -> coalesced global write ----
    __syncthreads();
    {
        char* Sp = smem;   // reuse buffer A0 (48 KB for 192 rows)
#pragma unroll
        for (int nt = 0; nt < 8; ++nt) {
            int col = nt * 8 + le * 2;
            int q = col >> 2, e = col & 3;
#pragma unroll
            for (int t = 0; t < 3; ++t) {
                int row = warp * 48 + t * 16 + lr;
                uint32_t o0 = (swz4(row, q) << 4) + (uint32_t)(e * 4);
                *(float2*)(Sp + o0)        = make_float2(acc[nt][t][0], acc[nt][t][1]);
                *(float2*)(Sp + o0 + 2048) = make_float2(acc[nt][t][2], acc[nt][t][3]);
            }
        }
    }
    __syncthreads();
    {
        const char* Sp = smem;
#pragma unroll
        for (int it = 0; it < 24; ++it) {
            int rl = (tid >> 4) + it * 8;
            int q = tid & 15;
            float4 v = *(const float4*)(Sp + (swz4(rl, q) << 4));
            int gr = cb + rl;
            if (gr < n) ((float4*)out)[(size_t)gr * 16 + q] = v;
        }
    }
}

// ---------------------------------------------------------------------------
__global__ void bn_relu_kernel(float* __restrict__ out,
                               const float* __restrict__ gamma,
                               const float* __restrict__ beta,
                               int n) {
    __shared__ float sc[COUT], bi[COUT];
    const int tid = threadIdx.x;
    if (tid < COUT) {
        float inv_n = 1.0f / (float)n;
        float mean = g_stats[tid] * inv_n;
        float var = fmaxf(g_stats[64 + tid] * inv_n - mean * mean, 0.0f);
        float inv = rsqrtf(var + BN_EPS);
        float scl = gamma[tid] * inv;
        sc[tid] = scl;
        bi[tid] = beta[tid] - mean * scl;
    }
    __syncthreads();

    const int total = n * (COUT / 4);
    float4* o4 = (float4*)out;
    for (int i = blockIdx.x * blockDim.x + tid; i < total;
         i += gridDim.x * blockDim.x) {
        float4 v = o4[i];
        int c = (i & 15) << 2;
        v.x = fmaxf(fmaf(v.x, sc[c],     bi[c]),     0.f);
        v.y = fmaxf(fmaf(v.y, sc[c + 1], bi[c + 1]), 0.f);
        v.z = fmaxf(fmaf(v.z, sc[c + 2], bi[c + 2]), 0.f);
        v.w = fmaxf(fmaf(v.w, sc[c + 3], bi[c + 3]), 0.f);
        o4[i] = v;
    }
}

// ---------------------------------------------------------------------------
extern "C" void kernel_launch(void* const* d_in, const int* in_sizes, int n_in,
                              void* d_out, int out_size) {
    const float* feats = (const float*)d_in[0];
    const float* Wg    = (const float*)d_in[1];
    const float* gamma = (const float*)d_in[2];
    const float* beta  = (const float*)d_in[3];
    const int*   nbr   = (const int*)d_in[4];
    const int*   mask  = (const int*)d_in[5];
    float* out = (float*)d_out;

    const int n  = in_sizes[0] / CIN;              // 200000
    const int kk = in_sizes[1] / (CIN * COUT);     // 27

    cudaFuncSetAttribute(conv_kernel,
                         cudaFuncAttributeMaxDynamicSharedMemorySize,
                         SMEM_BYTES);

    zero_stats_kernel<<<1, 128>>>();
    prep_w_kernel<<<kk, 256>>>(Wg);

    const int grid = (n + M_TILE - 1) / M_TILE;    // 1042
    conv_kernel<<<grid, CTA, SMEM_BYTES>>>(feats, nbr, mask, out, n, kk);

    int bn_grid = (n * (COUT / 4) + 255) / 256;
    if (bn_grid > 1184) bn_grid = 1184;
    bn_relu_kernel<<<bn_grid, 256>>>(out, gamma, beta, n);
}

// round 12
// speedup vs baseline: 1.1694x; 1.0013x over previous
#include <cuda_runtime.h>
#include <cuda_fp16.h>
#include <cstdint>

// ---------------------------------------------------------------------------
// BasicConvolutionBlock: sparse conv (gather-GEMM, K=27, Cin=Cout=64) + BN + ReLU
// fp16 mma.sync m16n8k16, f32 accumulate (compute_100-safe).
// CTA=256 (8 warps x 16 rows), M_TILE=128, occ 2, 1 sync per k (R8 regime).
// A: LDG f32 -> cvt fp16 -> STS (masked rows -> zeros). B: pre-converted fp16 W^T.
//   d_in[0] feats [N,64] f32      d_in[1] W [27,64,64] f32
//   d_in[2] gamma [64]            d_in[3] beta [64]
//   d_in[4] nbr_idx [27,N] i32    d_in[5] mask [27,N] i32
// out: [N,64] f32
// ---------------------------------------------------------------------------

#define CIN   64
#define COUT  64
#define MAXK  27
#define M_TILE 128
#define CTA   256
#define BN_EPS 1e-5f

// dynamic smem: A fp16 double-buffer (2 x 16KB) + B fp16 double-buffer (2 x 8KB)
#define A_OFF0 0u
#define A_OFF1 16384u
#define B_OFF0 32768u
#define B_OFF1 40960u
#define SMEM_BYTES 49152
// epilogue reuses [0, 32KB) as a 128x64 f32 tile

__device__ float  g_stats[128];                  // [0:64) sum, [64:128) sumsq
__device__ __half g_wt[MAXK * CIN * COUT];       // fp16 W, transposed [k][cout][cin]

// ---------------- helpers ---------------------------------------------------
__device__ __forceinline__ uint32_t smem_u32(const void* p) {
    uint32_t a;
    asm("{ .reg .u64 t; cvta.to.shared.u64 t, %1; cvt.u32.u64 %0, t; }"
        : "=r"(a) : "l"(p));
    return a;
}

__device__ __forceinline__ void cpa16(uint32_t dst, const void* src) {
    asm volatile("cp.async.cg.shared.global [%0], [%1], 16;"
                 :: "r"(dst), "l"(src) : "memory");
}
#define CP_COMMIT() asm volatile("cp.async.commit_group;" ::: "memory")
#define CP_WAIT0()  asm volatile("cp.async.wait_group 0;" ::: "memory")

__device__ __forceinline__ uint32_t f2h2(float lo, float hi) {
    __half2 h = __floats2half2_rn(lo, hi);      // lo -> .x (low half)
    return *reinterpret_cast<uint32_t*>(&h);
}

// f32 epilogue tile swizzle (float4 index): [128 rows][16 float4]
__device__ __forceinline__ uint32_t swz4(int r, int q) {
    return (uint32_t)(r * 16 + (q ^ (r & 7)));
}

// ---------------------------------------------------------------------------
__global__ void zero_stats_kernel() {
    int t = threadIdx.x;
    if (t < 128) g_stats[t] = 0.0f;
}

__global__ void prep_w_kernel(const float* __restrict__ w) {
    int k = blockIdx.x;
    const float* ws = w + (size_t)k * CIN * COUT;
    __half* wd = g_wt + (size_t)k * CIN * COUT;
    for (int e = threadIdx.x; e < CIN * COUT; e += blockDim.x) {
        int ci = e >> 6, co = e & 63;
        wd[co * 64 + ci] = __float2half_rn(ws[e]);   // transpose: [cout][cin]
    }
}

// ---------------------------------------------------------------------------
// Conv kernel: CTA = 256 thr (8 warps), tile = 128 rows, warp owns 16 rows.
// fp16 tiles in smem: rows of 64 halfs = 128B, XOR-swizzled 16B granules.
// ---------------------------------------------------------------------------
__global__ void __launch_bounds__(CTA, 2)
conv_kernel(const float* __restrict__ feats,
            const int* __restrict__ nbr,
            const int* __restrict__ mask,
            float*     __restrict__ out,
            int n, int kk) {
    extern __shared__ char smem[];
    const uint32_t sb = smem_u32(smem);

    const int tid  = threadIdx.x;
    const int warp = tid >> 5, lane = tid & 31;
    const int lr = lane >> 2, le = lane & 3;
    const int cb = blockIdx.x * M_TILE;

    const int r = tid >> 1;          // gather row (0..127), 2 threads per row
    const int h = tid & 1;           // which 32-col half of the row
    const int grow = cb + r;

    const uint32_t a_off[2] = {A_OFF0, A_OFF1};
    const uint32_t b_off[2] = {B_OFF0, B_OFF1};

    // --- idx/mask prefetch (depth 2) ----------------------------------------
    int pn = 0; uint32_t pv = 0;
    if (grow < n) { pv = (uint32_t)mask[grow]; pn = nbr[grow]; }

    const float4 fz = make_float4(0.f, 0.f, 0.f, 0.f);

    // --- prologue: stage A(0) (LDG+cvt+STS) and B(0) (cp.async) -------------
    {
        float4 f[8];
#pragma unroll
        for (int j = 0; j < 8; ++j) f[j] = fz;
        if (pv) {
            const float4* src = (const float4*)feats + (size_t)pn * 16 + h * 8;
#pragma unroll
            for (int j = 0; j < 8; ++j) f[j] = src[j];
        }
        // B(0) via cp.async: 512 granules of 16B, 2 per thread
        const char* wsrc = (const char*)g_wt;
#pragma unroll
        for (int i = 0; i < 2; ++i) {
            int g = tid + i * CTA;
            int co = g >> 3, q = g & 7;
            cpa16(sb + b_off[0] + (uint32_t)(co * 128 + ((q ^ (co & 7)) << 4)),
                  wsrc + g * 16);
        }
        CP_COMMIT();
        // cvt + STS A(0)
#pragma unroll
        for (int j = 0; j < 4; ++j) {
            uint4 u;
            u.x = f2h2(f[2 * j].x, f[2 * j].y);
            u.y = f2h2(f[2 * j].z, f[2 * j].w);
            u.z = f2h2(f[2 * j + 1].x, f[2 * j + 1].y);
            u.w = f2h2(f[2 * j + 1].z, f[2 * j + 1].w);
            *(uint4*)(smem + a_off[0] + r * 128 +
                      ((((h << 2) + j) ^ (r & 7)) << 4)) = u;
        }
    }
    if (kk > 1) {
        pv = 0; pn = 0;
        if (grow < n) { int o = n + grow; pv = (uint32_t)mask[o]; pn = nbr[o]; }
    }
    CP_WAIT0();
    __syncthreads();                 // A(0) + B(0) visible

    float acc[8][4];                 // [nt][frag]
#pragma unroll
    for (int nt = 0; nt < 8; ++nt)
#pragma unroll
        for (int j = 0; j < 4; ++j) acc[nt][j] = 0.0f;

    const int rbase = (warp << 4) + lr;   // warp row base + group row

    for (int k = 0; k < kk; ++k) {
        float4 f[8];
        // issue LDG A(k+1) + cp.async B(k+1)
        if (k + 1 < kk) {
#pragma unroll
            for (int j = 0; j < 8; ++j) f[j] = fz;
            if (pv) {
                const float4* src = (const float4*)feats + (size_t)pn * 16 + h * 8;
#pragma unroll
                for (int j = 0; j < 8; ++j) f[j] = src[j];
            }
            const char* wsrc = (const char*)(g_wt + (size_t)(k + 1) * CIN * COUT);
            const uint32_t bb = sb + b_off[(k + 1) & 1];
#pragma unroll
            for (int i = 0; i < 2; ++i) {
                int g = tid + i * CTA;
                int co = g >> 3, q = g & 7;
                cpa16(bb + (uint32_t)(co * 128 + ((q ^ (co & 7)) << 4)),
                      wsrc + g * 16);
            }
            CP_COMMIT();
        }
        // prefetch idx/mask for stage k+2
        if (k + 2 < kk) {
            pv = 0; pn = 0;
            if (grow < n) { int o = (k + 2) * n + grow; pv = (uint32_t)mask[o]; pn = nbr[o]; }
        }

        // ---- compute k from buffers k&1 ----
        const char* Ap = smem + a_off[k & 1];
        const char* Bp = smem + b_off[k & 1];
#pragma unroll
        for (int ks = 0; ks < 4; ++ks) {
            const uint32_t g0 = (uint32_t)((2 * ks) ^ lr) << 4;
            const uint32_t g1 = (uint32_t)((2 * ks + 1) ^ lr) << 4;
            const uint32_t ao = (uint32_t)(rbase << 7) + (uint32_t)(le << 2);
            uint32_t a0 = *(const uint32_t*)(Ap + ao + g0);
            uint32_t a1 = *(const uint32_t*)(Ap + ao + g0 + 1024);
            uint32_t a2 = *(const uint32_t*)(Ap + ao + g1);
            uint32_t a3 = *(const uint32_t*)(Ap + ao + g1 + 1024);
#pragma unroll
            for (int nt = 0; nt < 8; ++nt) {
                const uint32_t bo = (uint32_t)((nt * 8 + lr) << 7) + (uint32_t)(le << 2);
                uint32_t b0 = *(const uint32_t*)(Bp + bo + g0);
                uint32_t b1 = *(const uint32_t*)(Bp + bo + g1);
                asm volatile(
                    "mma.sync.aligned.m16n8k16.row.col.f32.f16.f16.f32 "
                    "{%0,%1,%2,%3}, {%4,%5,%6,%7}, {%8,%9}, {%0,%1,%2,%3};"
                    : "+f"(acc[nt][0]), "+f"(acc[nt][1]),
                      "+f"(acc[nt][2]), "+f"(acc[nt][3])
                    : "r"(a0), "r"(a1), "r"(a2), "r"(a3), "r"(b0), "r"(b1));
            }
        }

        // ---- cvt + STS A(k+1) into buf (k+1)&1; wait B; single sync --------
        if (k + 1 < kk) {
            const uint32_t ab = a_off[(k + 1) & 1];
#pragma unroll
            for (int j = 0; j < 4; ++j) {
                uint4 u;
                u.x = f2h2(f[2 * j].x, f[2 * j].y);
                u.y = f2h2(f[2 * j].z, f[2 * j].w);
                u.z = f2h2(f[2 * j + 1].x, f[2 * j + 1].y);
                u.w = f2h2(f[2 * j + 1].z, f[2 * j + 1].w);
                *(uint4*)(smem + ab + r * 128 +
                          ((((h << 2) + j) ^ (r & 7)) << 4)) = u;
            }
            CP_WAIT0();
            __syncthreads();
        }
    }

    // ---- BN partial stats from register fragments (invalid rows hold 0) ----
#pragma unroll
    for (int nt = 0; nt < 8; ++nt) {
        float s0 = acc[nt][0] + acc[nt][2];
        float q0 = acc[nt][0] * acc[nt][0] + acc[nt][2] * acc[nt][2];
        float s1 = acc[nt][1] + acc[nt][3];
        float q1 = acc[nt][1] * acc[nt][1] + acc[nt][3] * acc[nt][3];
#pragma unroll
        for (int d = 4; d <= 16; d <<= 1) {
            s0 += __shfl_xor_sync(0xffffffffu, s0, d);
            q0 += __shfl_xor_sync(0xffffffffu, q0, d);
            s1 += __shfl_xor_sync(0xffffffffu, s1, d);
            q1 += __shfl_xor_sync(0xffffffffu, q1, d);
        }
        if (lane < 4) {
            int c0 = nt * 8 + lane * 2;
            atomicAdd(&g_stats[c0], s0);      atomicAdd(&g_stats[64 + c0], q0);
            atomicAdd(&g_stats[c0 + 1], s1);  atomicAdd(&g_stats[64 + c0 + 1], q1);
        }
    }

    // ---- fragments -> f32 smem tile (swizzled) -> coalesced global write ---
    __syncthreads();                 // everyone done reading A/B buffers
    {
        char* Sp = smem;             // [0,32KB) as 128x64 f32 tile
#pragma unroll
        for (int nt = 0; nt < 8; ++nt) {
            int col = nt * 8 + le * 2;
            int q = col >> 2, e = col & 3;
            uint32_t o0 = (swz4(rbase, q) << 4) + (uint32_t)(e * 4);
            *(float2*)(Sp + o0)        = make_float2(acc[nt][0], acc[nt][1]);
            *(float2*)(Sp + o0 + 2048) = make_float2(acc[nt][2], acc[nt][3]);
        }
    }
    __syncthreads();
    {
        const char* Sp = smem;
#pragma unroll
        for (int it = 0; it < 8; ++it) {
            int idx = tid + it * CTA;          // 0..2047 float4s
            int rl = idx >> 4, q = idx & 15;
            float4 v = *(const float4*)(Sp + (swz4(rl, q) << 4));
            int gr = cb + rl;
            if (gr < n) ((float4*)out)[(size_t)gr * 16 + q] = v;
        }
    }
}

// ---------------------------------------------------------------------------
__global__ void bn_relu_kernel(float* __restrict__ out,
                               const float* __restrict__ gamma,
                               const float* __restrict__ beta,
                               int n) {
    __shared__ float sc[COUT], bi[COUT];
    const int tid = threadIdx.x;
    if (tid < COUT) {
        float inv_n = 1.0f / (float)n;
        float mean = g_stats[tid] * inv_n;
        float var = fmaxf(g_stats[64 + tid] * inv_n - mean * mean, 0.0f);
        float inv = rsqrtf(var + BN_EPS);
        float scl = gamma[tid] * inv;
        sc[tid] = scl;
        bi[tid] = beta[tid] - mean * scl;
    }
    __syncthreads();

    const int total = n * (COUT / 4);
    float4* o4 = (float4*)out;
    for (int i = blockIdx.x * blockDim.x + tid; i < total;
         i += gridDim.x * blockDim.x) {
        float4 v = o4[i];
        int c = (i & 15) << 2;
        v.x = fmaxf(fmaf(v.x, sc[c],     bi[c]),     0.f);
        v.y = fmaxf(fmaf(v.y, sc[c + 1], bi[c + 1]), 0.f);
        v.z = fmaxf(fmaf(v.z, sc[c + 2], bi[c + 2]), 0.f);
        v.w = fmaxf(fmaf(v.w, sc[c + 3], bi[c + 3]), 0.f);
        o4[i] = v;
    }
}

// ---------------------------------------------------------------------------
extern "C" void kernel_launch(void* const* d_in, const int* in_sizes, int n_in,
                              void* d_out, int out_size) {
    const float* feats = (const float*)d_in[0];
    const float* Wg    = (const float*)d_in[1];
    const float* gamma = (const float*)d_in[2];
    const float* beta  = (const float*)d_in[3];
    const int*   nbr   = (const int*)d_in[4];
    const int*   mask  = (const int*)d_in[5];
    float* out = (float*)d_out;

    const int n  = in_sizes[0] / CIN;              // 200000
    const int kk = in_sizes[1] / (CIN * COUT);     // 27

    cudaFuncSetAttribute(conv_kernel,
                         cudaFuncAttributeMaxDynamicSharedMemorySize,
                         SMEM_BYTES);

    zero_stats_kernel<<<1, 128>>>();
    prep_w_kernel<<<kk, 256>>>(Wg);

    const int grid = (n + M_TILE - 1) / M_TILE;    // 1563
    conv_kernel<<<grid, CTA, SMEM_BYTES>>>(feats, nbr, mask, out, n, kk);

    int bn_grid = (n * (COUT / 4) + 255) / 256;
    if (bn_grid > 1184) bn_grid = 1184;
    bn_relu_kernel<<<bn_grid, 256>>>(out, gamma, beta, n);
}